// round 1
// baseline (speedup 1.0000x reference)
#include <cuda_runtime.h>
#include <cstdint>

#define N_NODES 50000
#define DIM     128
#define M_EDGES 800000

// Scratch (allocation-free rule: __device__ globals). 16B-aligned for float4.
__device__ __align__(256) float g_x0[(size_t)N_NODES * DIM];
__device__ __align__(256) float g_xn[(size_t)N_NODES * DIM];
__device__ __align__(256) float g_c [(size_t)N_NODES * DIM];
__device__ __align__(256) float g_cn[(size_t)N_NODES * DIM];
__device__ int g_is64;

// ---------------------------------------------------------------------------
// Detect whether edge_index is int64 (all high 32-bit words of first entries 0)
// or int32 (odd words are random values in [0, 50000)).
// ---------------------------------------------------------------------------
__global__ void detect_dtype_kernel(const unsigned int* __restrict__ e) {
    if (blockIdx.x == 0 && threadIdx.x == 0) {
        int is64 = 1;
        #pragma unroll 4
        for (int i = 0; i < 256; i++) {
            if (e[2 * i + 1] != 0u) { is64 = 0; break; }
        }
        g_is64 = is64;
    }
}

// ---------------------------------------------------------------------------
// GEMM: C[nrows,128] = A[nrows,128] @ W[128,128] + bias.  Warp computes 4 rows.
// ---------------------------------------------------------------------------
__device__ __forceinline__ void fma4(float4& acc, float a, const float4& w) {
    acc.x += a * w.x; acc.y += a * w.y; acc.z += a * w.z; acc.w += a * w.w;
}

__global__ void gemm_bias_kernel(const float* __restrict__ A,
                                 const float* __restrict__ W,
                                 const float* __restrict__ bias,
                                 float* __restrict__ C, int nrows) {
    int gwarp = (blockIdx.x * blockDim.x + threadIdx.x) >> 5;
    int lane  = threadIdx.x & 31;
    int row0  = gwarp * 4;
    if (row0 >= nrows) return;

    float4 acc0 = {0.f,0.f,0.f,0.f}, acc1 = {0.f,0.f,0.f,0.f};
    float4 acc2 = {0.f,0.f,0.f,0.f}, acc3 = {0.f,0.f,0.f,0.f};
    const float* a = A + (size_t)row0 * DIM;

    #pragma unroll 2
    for (int k = 0; k < DIM; k += 4) {
        float4 a0 = *(const float4*)(a + 0 * DIM + k);
        float4 a1 = *(const float4*)(a + 1 * DIM + k);
        float4 a2 = *(const float4*)(a + 2 * DIM + k);
        float4 a3 = *(const float4*)(a + 3 * DIM + k);

        float4 w;
        w = *(const float4*)(W + (size_t)(k + 0) * DIM + lane * 4);
        fma4(acc0, a0.x, w); fma4(acc1, a1.x, w); fma4(acc2, a2.x, w); fma4(acc3, a3.x, w);
        w = *(const float4*)(W + (size_t)(k + 1) * DIM + lane * 4);
        fma4(acc0, a0.y, w); fma4(acc1, a1.y, w); fma4(acc2, a2.y, w); fma4(acc3, a3.y, w);
        w = *(const float4*)(W + (size_t)(k + 2) * DIM + lane * 4);
        fma4(acc0, a0.z, w); fma4(acc1, a1.z, w); fma4(acc2, a2.z, w); fma4(acc3, a3.z, w);
        w = *(const float4*)(W + (size_t)(k + 3) * DIM + lane * 4);
        fma4(acc0, a0.w, w); fma4(acc1, a1.w, w); fma4(acc2, a2.w, w); fma4(acc3, a3.w, w);
    }

    float4 bv = *(const float4*)(bias + lane * 4);
    acc0.x += bv.x; acc0.y += bv.y; acc0.z += bv.z; acc0.w += bv.w;
    acc1.x += bv.x; acc1.y += bv.y; acc1.z += bv.z; acc1.w += bv.w;
    acc2.x += bv.x; acc2.y += bv.y; acc2.z += bv.z; acc2.w += bv.w;
    acc3.x += bv.x; acc3.y += bv.y; acc3.z += bv.z; acc3.w += bv.w;

    *(float4*)(C + (size_t)(row0 + 0) * DIM + lane * 4) = acc0;
    *(float4*)(C + (size_t)(row0 + 1) * DIM + lane * 4) = acc1;
    *(float4*)(C + (size_t)(row0 + 2) * DIM + lane * 4) = acc2;
    *(float4*)(C + (size_t)(row0 + 3) * DIM + lane * 4) = acc3;
}

// ---------------------------------------------------------------------------
// Channel normalization: per node, 4 channels of 32; F.normalize semantics
// v / max(||v||, 1e-12).  One warp per node; lane owns 4 consecutive floats
// (8 lanes per channel).
// ---------------------------------------------------------------------------
__global__ void chan_norm_kernel(const float* __restrict__ in,
                                 float* __restrict__ out) {
    int gw   = (blockIdx.x * blockDim.x + threadIdx.x) >> 5;
    int lane = threadIdx.x & 31;
    if (gw >= N_NODES) return;

    float4 v = *(const float4*)(in + (size_t)gw * DIM + lane * 4);
    float ss = v.x * v.x + v.y * v.y + v.z * v.z + v.w * v.w;
    ss += __shfl_xor_sync(0xffffffffu, ss, 1);
    ss += __shfl_xor_sync(0xffffffffu, ss, 2);
    ss += __shfl_xor_sync(0xffffffffu, ss, 4);   // channel = lane >> 3
    float inv = 1.0f / fmaxf(sqrtf(ss), 1e-12f);
    float4 o;
    o.x = v.x * inv; o.y = v.y * inv; o.z = v.z * inv; o.w = v.w * inv;
    *(float4*)(out + (size_t)gw * DIM + lane * 4) = o;
}

// ---------------------------------------------------------------------------
// Routing edge pass: one warp per edge.
//   s[a]   = sum_{j<4} c[trg][4a+j]          (lane a's float4 sum)
//   p[k]   = sum_a z[k,a]*s[a],  z = xn[src] (k = lane>>3 group reduce)
//   p      = softmax_k(p)
//   cnext[trg] += p[k] * z      (vector red.add.v4.f32)
// ---------------------------------------------------------------------------
__global__ void edge_route_kernel(const float* __restrict__ c,
                                  const float* __restrict__ xn,
                                  float* __restrict__ cnext,
                                  const int* __restrict__ eidx) {
    int gw   = (blockIdx.x * blockDim.x + threadIdx.x) >> 5;
    int lane = threadIdx.x & 31;
    if (gw >= M_EDGES) return;

    int src, trg;
    if (g_is64) {   // int64 edge_index: read low 32-bit words
        src = eidx[2 * (size_t)gw];
        trg = eidx[2 * ((size_t)M_EDGES + gw)];
    } else {
        src = eidx[gw];
        trg = eidx[M_EDGES + gw];
    }

    const float4 cv = *(const float4*)(c  + (size_t)trg * DIM + lane * 4);
    const float4 zv = *(const float4*)(xn + (size_t)src * DIM + lane * 4);

    // s[lane] = group-of-4 sum of c[trg]
    float s = cv.x + cv.y + cv.z + cv.w;

    // lane's z elements are indices 4*lane..4*lane+3 -> need s[(4*lane)&31 + j]
    int base = (lane * 4) & 31;
    float s0 = __shfl_sync(0xffffffffu, s, base + 0);
    float s1 = __shfl_sync(0xffffffffu, s, base + 1);
    float s2 = __shfl_sync(0xffffffffu, s, base + 2);
    float s3 = __shfl_sync(0xffffffffu, s, base + 3);

    float part = zv.x * s0 + zv.y * s1 + zv.z * s2 + zv.w * s3;
    // reduce within 8-lane channel group (channel = lane>>3)
    part += __shfl_xor_sync(0xffffffffu, part, 1);
    part += __shfl_xor_sync(0xffffffffu, part, 2);
    part += __shfl_xor_sync(0xffffffffu, part, 4);

    // softmax across the 4 channel groups (TAU = 1)
    float mx = part;
    mx = fmaxf(mx, __shfl_xor_sync(0xffffffffu, mx, 8));
    mx = fmaxf(mx, __shfl_xor_sync(0xffffffffu, mx, 16));
    float e  = __expf(part - mx);
    float es = e;
    es += __shfl_xor_sync(0xffffffffu, es, 8);
    es += __shfl_xor_sync(0xffffffffu, es, 16);
    float pk = e / es;

    float wx = pk * zv.x, wy = pk * zv.y, wz = pk * zv.z, ww = pk * zv.w;
    float* dst = cnext + (size_t)trg * DIM + lane * 4;
    asm volatile("red.global.add.v4.f32 [%0], {%1, %2, %3, %4};"
                 :: "l"(dst), "f"(wx), "f"(wy), "f"(wz), "f"(ww)
                 : "memory");
}

// ---------------------------------------------------------------------------
// Launch
// ---------------------------------------------------------------------------
extern "C" void kernel_launch(void* const* d_in, const int* in_sizes, int n_in,
                              void* d_out, int out_size) {
    const float* feat  = (const float*)d_in[0];
    const int*   eidx  = (const int*)  d_in[1];   // int32 OR low-words of int64 (detected)
    const float* lin_w = (const float*)d_in[2];
    const float* lin_b = (const float*)d_in[3];
    const float* mlp_w = (const float*)d_in[4];
    const float* mlp_b = (const float*)d_in[5];
    float*       out   = (float*)d_out;

    float *x0, *xn, *c, *cn;
    cudaGetSymbolAddress((void**)&x0, g_x0);
    cudaGetSymbolAddress((void**)&xn, g_xn);
    cudaGetSymbolAddress((void**)&c,  g_c);
    cudaGetSymbolAddress((void**)&cn, g_cn);

    const size_t bytes = (size_t)N_NODES * DIM * sizeof(float);

    detect_dtype_kernel<<<1, 32>>>((const unsigned int*)d_in[1]);

    // x0 = feat @ lin_w + lin_b
    const int gemm_blocks = ((N_NODES / 4) + 7) / 8;        // 4 rows/warp, 8 warps/block
    gemm_bias_kernel<<<gemm_blocks, 256>>>(feat, lin_w, lin_b, x0, N_NODES);

    const int norm_blocks = N_NODES / 8;                    // 1 warp/node, 8 warps/block
    const int edge_blocks = M_EDGES / 8;                    // 1 warp/edge, 8 warps/block

    const float* cur = x0;
    for (int layer = 0; layer < 2; layer++) {
        chan_norm_kernel<<<norm_blocks, 256>>>(cur, xn);    // xn = normalize(cur)
        const float* cptr = xn;                             // c starts as xn
        for (int t = 0; t < 3; t++) {
            // cnext = xn (the "+ x" term), then scatter-add weight_sum
            cudaMemcpyAsync(cn, xn, bytes, cudaMemcpyDeviceToDevice, 0);
            edge_route_kernel<<<edge_blocks, 256>>>(cptr, xn, cn, eidx);
            if (t < 2) {
                chan_norm_kernel<<<norm_blocks, 256>>>(cn, c);
                cptr = c;
            }
        }
        cur = cn;   // layer output: unnormalized final c
    }

    // out = x_final @ mlp_w + mlp_b ; then x_final itself
    gemm_bias_kernel<<<gemm_blocks, 256>>>(cn, mlp_w, mlp_b, out, N_NODES);
    cudaMemcpyAsync(out + (size_t)N_NODES * DIM, cn, bytes,
                    cudaMemcpyDeviceToDevice, 0);
}

// round 2
// speedup vs baseline: 1.1358x; 1.1358x over previous
#include <cuda_runtime.h>
#include <cstdint>

#define N_NODES 50000
#define DIM     128
#define M_EDGES 800000
#define NF      ((size_t)N_NODES * DIM)

// Scratch (allocation-free rule: __device__ globals). 16B-aligned for float4.
__device__ __align__(256) float g_x0 [NF];                    // layer input / GEMM out
__device__ __align__(256) float g_xn0[NF];                    // xn ping
__device__ __align__(256) float g_xn1[NF];                    // xn pong
__device__ __align__(256) float g_acc[NF];                    // atomic accumulator
__device__ __align__(256) float g_s  [(size_t)N_NODES * 32];  // per-node group sums
__device__ int g_is64;

// ---------------------------------------------------------------------------
// Detect int64 vs int32 edge_index (high 32-bit words all zero => int64).
// ---------------------------------------------------------------------------
__global__ void detect_dtype_kernel(const unsigned int* __restrict__ e) {
    if (blockIdx.x == 0 && threadIdx.x == 0) {
        int is64 = 1;
        for (int i = 0; i < 256; i++) {
            if (e[2 * i + 1] != 0u) { is64 = 0; break; }
        }
        g_is64 = is64;
    }
}

// ---------------------------------------------------------------------------
// GEMM: C[nrows,128] = A[nrows,128] @ W[128,128] + bias. Warp computes 4 rows.
// ---------------------------------------------------------------------------
__device__ __forceinline__ void fma4(float4& acc, float a, const float4& w) {
    acc.x += a * w.x; acc.y += a * w.y; acc.z += a * w.z; acc.w += a * w.w;
}

__global__ void gemm_bias_kernel(const float* __restrict__ A,
                                 const float* __restrict__ W,
                                 const float* __restrict__ bias,
                                 float* __restrict__ C, int nrows) {
    int gwarp = (blockIdx.x * blockDim.x + threadIdx.x) >> 5;
    int lane  = threadIdx.x & 31;
    int row0  = gwarp * 4;
    if (row0 >= nrows) return;

    float4 acc0 = {0,0,0,0}, acc1 = {0,0,0,0}, acc2 = {0,0,0,0}, acc3 = {0,0,0,0};
    const float* a = A + (size_t)row0 * DIM;

    #pragma unroll 2
    for (int k = 0; k < DIM; k += 4) {
        float4 a0 = *(const float4*)(a + 0 * DIM + k);
        float4 a1 = *(const float4*)(a + 1 * DIM + k);
        float4 a2 = *(const float4*)(a + 2 * DIM + k);
        float4 a3 = *(const float4*)(a + 3 * DIM + k);

        float4 w;
        w = *(const float4*)(W + (size_t)(k + 0) * DIM + lane * 4);
        fma4(acc0, a0.x, w); fma4(acc1, a1.x, w); fma4(acc2, a2.x, w); fma4(acc3, a3.x, w);
        w = *(const float4*)(W + (size_t)(k + 1) * DIM + lane * 4);
        fma4(acc0, a0.y, w); fma4(acc1, a1.y, w); fma4(acc2, a2.y, w); fma4(acc3, a3.y, w);
        w = *(const float4*)(W + (size_t)(k + 2) * DIM + lane * 4);
        fma4(acc0, a0.z, w); fma4(acc1, a1.z, w); fma4(acc2, a2.z, w); fma4(acc3, a3.z, w);
        w = *(const float4*)(W + (size_t)(k + 3) * DIM + lane * 4);
        fma4(acc0, a0.w, w); fma4(acc1, a1.w, w); fma4(acc2, a2.w, w); fma4(acc3, a3.w, w);
    }

    float4 bv = *(const float4*)(bias + lane * 4);
    acc0.x += bv.x; acc0.y += bv.y; acc0.z += bv.z; acc0.w += bv.w;
    acc1.x += bv.x; acc1.y += bv.y; acc1.z += bv.z; acc1.w += bv.w;
    acc2.x += bv.x; acc2.y += bv.y; acc2.z += bv.z; acc2.w += bv.w;
    acc3.x += bv.x; acc3.y += bv.y; acc3.z += bv.z; acc3.w += bv.w;

    *(float4*)(C + (size_t)(row0 + 0) * DIM + lane * 4) = acc0;
    *(float4*)(C + (size_t)(row0 + 1) * DIM + lane * 4) = acc1;
    *(float4*)(C + (size_t)(row0 + 2) * DIM + lane * 4) = acc2;
    *(float4*)(C + (size_t)(row0 + 3) * DIM + lane * 4) = acc3;
}

// ---------------------------------------------------------------------------
// Layer-start kernel: v = in1 (+ in2); xn = channel-normalize(v);
// s[a] = group-of-4 sum of xn; acc := 0.  One warp per node.
// ---------------------------------------------------------------------------
__global__ void norm_s_kernel(const float* __restrict__ in1,
                              const float* __restrict__ in2,   // nullable
                              float* __restrict__ xn,
                              float* __restrict__ s_arr,
                              float* __restrict__ acc) {
    int gw   = (blockIdx.x * blockDim.x + threadIdx.x) >> 5;
    int lane = threadIdx.x & 31;
    if (gw >= N_NODES) return;

    size_t off = (size_t)gw * DIM + lane * 4;
    float4 v = *(const float4*)(in1 + off);
    if (in2) {
        float4 u = *(const float4*)(in2 + off);
        v.x += u.x; v.y += u.y; v.z += u.z; v.w += u.w;
    }
    float ss = v.x * v.x + v.y * v.y + v.z * v.z + v.w * v.w;
    ss += __shfl_xor_sync(0xffffffffu, ss, 1);
    ss += __shfl_xor_sync(0xffffffffu, ss, 2);
    ss += __shfl_xor_sync(0xffffffffu, ss, 4);   // channel = lane >> 3
    float inv = 1.0f / fmaxf(sqrtf(ss), 1e-12f);
    float4 o = {v.x * inv, v.y * inv, v.z * inv, v.w * inv};
    *(float4*)(xn + off) = o;
    s_arr[(size_t)gw * 32 + lane] = o.x + o.y + o.z + o.w;
    *(float4*)(acc + off) = make_float4(0.f, 0.f, 0.f, 0.f);
}

// ---------------------------------------------------------------------------
// Post-edge s update (for next routing iter): c = normalize(acc + xn);
// write ONLY s (32 floats) and re-zero acc. Full c never materialized.
// ---------------------------------------------------------------------------
__global__ void s_update_kernel(const float* __restrict__ acc,
                                const float* __restrict__ xn,
                                float* __restrict__ s_arr,
                                float* __restrict__ acc_zero) {
    int gw   = (blockIdx.x * blockDim.x + threadIdx.x) >> 5;
    int lane = threadIdx.x & 31;
    if (gw >= N_NODES) return;

    size_t off = (size_t)gw * DIM + lane * 4;
    float4 a = *(const float4*)(acc + off);
    float4 u = *(const float4*)(xn + off);
    float4 v = {a.x + u.x, a.y + u.y, a.z + u.z, a.w + u.w};
    float ss = v.x * v.x + v.y * v.y + v.z * v.z + v.w * v.w;
    ss += __shfl_xor_sync(0xffffffffu, ss, 1);
    ss += __shfl_xor_sync(0xffffffffu, ss, 2);
    ss += __shfl_xor_sync(0xffffffffu, ss, 4);
    float inv = 1.0f / fmaxf(sqrtf(ss), 1e-12f);
    s_arr[(size_t)gw * 32 + lane] = (v.x + v.y + v.z + v.w) * inv;
    *(float4*)(acc_zero + off) = make_float4(0.f, 0.f, 0.f, 0.f);
}

// ---------------------------------------------------------------------------
// Combine: out = acc + xn  (final unnormalized layer output)
// ---------------------------------------------------------------------------
__global__ void combine_kernel(const float* __restrict__ acc,
                               const float* __restrict__ xn,
                               float* __restrict__ out) {
    size_t i = (size_t)blockIdx.x * blockDim.x + threadIdx.x;
    if (i >= NF / 4) return;
    float4 a = ((const float4*)acc)[i];
    float4 u = ((const float4*)xn)[i];
    ((float4*)out)[i] = make_float4(a.x + u.x, a.y + u.y, a.z + u.z, a.w + u.w);
}

// ---------------------------------------------------------------------------
// Routing edge pass: one warp per edge.
//   sv  = s[trg] float4 slice (precomputed group sums of normalized c)
//   p_k = Σ z*s over channel group, softmax over K=4
//   acc[trg] += p_k * z   via red.global.add.v4.f32
// ---------------------------------------------------------------------------
__global__ void edge_route_kernel(const float* __restrict__ s_arr,
                                  const float* __restrict__ xn,
                                  float* __restrict__ acc,
                                  const int* __restrict__ eidx) {
    int gw   = (blockIdx.x * blockDim.x + threadIdx.x) >> 5;
    int lane = threadIdx.x & 31;
    if (gw >= M_EDGES) return;

    int src, trg;
    if (g_is64) {
        src = eidx[2 * (size_t)gw];
        trg = eidx[2 * ((size_t)M_EDGES + gw)];
    } else {
        src = eidx[gw];
        trg = eidx[M_EDGES + gw];
    }

    float4 zv = *(const float4*)(xn + (size_t)src * DIM + lane * 4);
    float4 sv = *(const float4*)(s_arr + (size_t)trg * 32 + (lane & 7) * 4);

    float part = zv.x * sv.x + zv.y * sv.y + zv.z * sv.z + zv.w * sv.w;
    part += __shfl_xor_sync(0xffffffffu, part, 1);
    part += __shfl_xor_sync(0xffffffffu, part, 2);
    part += __shfl_xor_sync(0xffffffffu, part, 4);   // per-channel dot (8 lanes)

    // softmax over the 4 channel groups (TAU = 1)
    float mx = fmaxf(part, __shfl_xor_sync(0xffffffffu, part, 8));
    mx = fmaxf(mx, __shfl_xor_sync(0xffffffffu, mx, 16));
    float e  = __expf(part - mx);
    float es = e;
    es += __shfl_xor_sync(0xffffffffu, es, 8);
    es += __shfl_xor_sync(0xffffffffu, es, 16);
    float pk = e / es;

    float wx = pk * zv.x, wy = pk * zv.y, wz = pk * zv.z, ww = pk * zv.w;
    float* dst = acc + (size_t)trg * DIM + lane * 4;
    asm volatile("red.global.add.v4.f32 [%0], {%1, %2, %3, %4};"
                 :: "l"(dst), "f"(wx), "f"(wy), "f"(wz), "f"(ww)
                 : "memory");
}

// ---------------------------------------------------------------------------
// Launch
// ---------------------------------------------------------------------------
extern "C" void kernel_launch(void* const* d_in, const int* in_sizes, int n_in,
                              void* d_out, int out_size) {
    const float* feat  = (const float*)d_in[0];
    const int*   eidx  = (const int*)  d_in[1];
    const float* lin_w = (const float*)d_in[2];
    const float* lin_b = (const float*)d_in[3];
    const float* mlp_w = (const float*)d_in[4];
    const float* mlp_b = (const float*)d_in[5];
    float*       out   = (float*)d_out;

    float *x0, *xn0, *xn1, *acc, *sarr;
    cudaGetSymbolAddress((void**)&x0,  g_x0);
    cudaGetSymbolAddress((void**)&xn0, g_xn0);
    cudaGetSymbolAddress((void**)&xn1, g_xn1);
    cudaGetSymbolAddress((void**)&acc, g_acc);
    cudaGetSymbolAddress((void**)&sarr, g_s);

    detect_dtype_kernel<<<1, 32>>>((const unsigned int*)d_in[1]);

    const int gemm_blocks = ((N_NODES / 4) + 7) / 8;   // 4 rows/warp, 8 warps/block
    const int node_blocks = N_NODES / 8;               // 1 warp/node
    const int edge_blocks = M_EDGES / 8;               // 1 warp/edge

    // x0 = feat @ lin_w + lin_b
    gemm_bias_kernel<<<gemm_blocks, 256>>>(feat, lin_w, lin_b, x0, N_NODES);

    float* xn_cur = xn0;
    for (int layer = 0; layer < 2; layer++) {
        if (layer == 0)
            norm_s_kernel<<<node_blocks, 256>>>(x0, nullptr, xn_cur, sarr, acc);
        else
            norm_s_kernel<<<node_blocks, 256>>>(acc, xn0, xn_cur, sarr, acc);

        for (int t = 0; t < 3; t++) {
            edge_route_kernel<<<edge_blocks, 256>>>(sarr, xn_cur, acc, eidx);
            if (t < 2)
                s_update_kernel<<<node_blocks, 256>>>(acc, xn_cur, sarr, acc);
        }
        xn_cur = xn1;  // layer 1 uses the pong buffer (layer-0 xn0 still needed as input)
    }

    // x_final = acc + xn1  -> written straight into the output tail
    float* out_tail = out + NF;
    combine_kernel<<<(int)((NF / 4 + 255) / 256), 256>>>(acc, xn1, out_tail);

    // out_head = x_final @ mlp_w + mlp_b
    gemm_bias_kernel<<<gemm_blocks, 256>>>(out_tail, mlp_w, mlp_b, out, N_NODES);
}

// round 4
// speedup vs baseline: 1.5323x; 1.3491x over previous
#include <cuda_runtime.h>
#include <cstdint>

#define N_NODES 50000
#define DIM     128
#define M_EDGES 800000
#define NF      ((size_t)N_NODES * DIM)
#define CHUNK   512
#define NCHUNKS ((N_NODES + CHUNK - 1) / CHUNK)   // 98

// Scratch (__device__ globals; no allocations allowed).
__device__ __align__(256) float g_x0 [NF];                    // layer io buffer
__device__ __align__(256) float g_xn [NF];                    // normalized features
__device__ __align__(256) float g_s  [(size_t)N_NODES * 32];  // per-node group sums
__device__ int g_deg [N_NODES];
__device__ int g_cnt [N_NODES];
__device__ int g_scan[N_NODES];     // within-chunk exclusive scan of deg
__device__ int g_bsum[NCHUNKS];
__device__ int g_boff[NCHUNKS];
__device__ int g_esrc[M_EDGES];     // src ids, sorted by trg (CSR payload)
__device__ int g_is64;

// ---------------------------------------------------------------------------
__global__ void detect_dtype_kernel(const unsigned int* __restrict__ e) {
    if (threadIdx.x == 0) {
        int is64 = 1;
        for (int i = 0; i < 256; i++)
            if (e[2 * i + 1] != 0u) { is64 = 0; break; }
        g_is64 = is64;
    }
}

// ---------------------------------------------------------------------------
// CSR build: histogram -> 2-level exclusive scan -> scatter.
// ---------------------------------------------------------------------------
__global__ void hist_kernel(const int* __restrict__ eidx, int* __restrict__ deg) {
    int e = blockIdx.x * blockDim.x + threadIdx.x;
    if (e >= M_EDGES) return;
    int trg = g_is64 ? eidx[2 * ((size_t)M_EDGES + e)] : eidx[M_EDGES + e];
    atomicAdd(&deg[trg], 1);
}

__global__ void scan_phase1(const int* __restrict__ deg,
                            int* __restrict__ scanned, int* __restrict__ bsum) {
    __shared__ int sm[CHUNK];
    int i = blockIdx.x * CHUNK + threadIdx.x;
    int v = (i < N_NODES) ? deg[i] : 0;
    sm[threadIdx.x] = v;
    __syncthreads();
    for (int off = 1; off < CHUNK; off <<= 1) {
        int t = (threadIdx.x >= off) ? sm[threadIdx.x - off] : 0;
        __syncthreads();
        sm[threadIdx.x] += t;
        __syncthreads();
    }
    if (i < N_NODES) scanned[i] = sm[threadIdx.x] - v;   // exclusive
    if (threadIdx.x == CHUNK - 1) bsum[blockIdx.x] = sm[CHUNK - 1];
}

__global__ void scan_phase2(const int* __restrict__ bsum, int* __restrict__ boff) {
    __shared__ int sm[128];
    int t = threadIdx.x;
    int v = (t < NCHUNKS) ? bsum[t] : 0;
    sm[t] = v;
    __syncthreads();
    for (int off = 1; off < 128; off <<= 1) {
        int u = (t >= off) ? sm[t - off] : 0;
        __syncthreads();
        sm[t] += u;
        __syncthreads();
    }
    if (t < NCHUNKS) boff[t] = sm[t] - v;   // exclusive
}

__global__ void scatter_kernel(const int* __restrict__ eidx,
                               const int* __restrict__ scanned,
                               const int* __restrict__ boff,
                               int* __restrict__ cnt, int* __restrict__ esrc) {
    int e = blockIdx.x * blockDim.x + threadIdx.x;
    if (e >= M_EDGES) return;
    int src, trg;
    if (g_is64) {
        src = eidx[2 * (size_t)e];
        trg = eidx[2 * ((size_t)M_EDGES + e)];
    } else {
        src = eidx[e];
        trg = eidx[M_EDGES + e];
    }
    int pos = scanned[trg] + boff[trg >> 9] + atomicAdd(&cnt[trg], 1);
    esrc[pos] = src;
}

// ---------------------------------------------------------------------------
// GEMM: C[nrows,128] = A[nrows,128] @ W[128,128] + bias. Warp computes 4 rows.
// ---------------------------------------------------------------------------
__device__ __forceinline__ void fma4(float4& acc, float a, const float4& w) {
    acc.x += a * w.x; acc.y += a * w.y; acc.z += a * w.z; acc.w += a * w.w;
}

__global__ void gemm_bias_kernel(const float* __restrict__ A,
                                 const float* __restrict__ W,
                                 const float* __restrict__ bias,
                                 float* __restrict__ C, int nrows) {
    int gwarp = (blockIdx.x * blockDim.x + threadIdx.x) >> 5;
    int lane  = threadIdx.x & 31;
    int row0  = gwarp * 4;
    if (row0 >= nrows) return;

    float4 acc0 = {0,0,0,0}, acc1 = {0,0,0,0}, acc2 = {0,0,0,0}, acc3 = {0,0,0,0};
    const float* a = A + (size_t)row0 * DIM;

    #pragma unroll 2
    for (int k = 0; k < DIM; k += 4) {
        float4 a0 = *(const float4*)(a + 0 * DIM + k);
        float4 a1 = *(const float4*)(a + 1 * DIM + k);
        float4 a2 = *(const float4*)(a + 2 * DIM + k);
        float4 a3 = *(const float4*)(a + 3 * DIM + k);
        float4 w;
        w = *(const float4*)(W + (size_t)(k + 0) * DIM + lane * 4);
        fma4(acc0, a0.x, w); fma4(acc1, a1.x, w); fma4(acc2, a2.x, w); fma4(acc3, a3.x, w);
        w = *(const float4*)(W + (size_t)(k + 1) * DIM + lane * 4);
        fma4(acc0, a0.y, w); fma4(acc1, a1.y, w); fma4(acc2, a2.y, w); fma4(acc3, a3.y, w);
        w = *(const float4*)(W + (size_t)(k + 2) * DIM + lane * 4);
        fma4(acc0, a0.z, w); fma4(acc1, a1.z, w); fma4(acc2, a2.z, w); fma4(acc3, a3.z, w);
        w = *(const float4*)(W + (size_t)(k + 3) * DIM + lane * 4);
        fma4(acc0, a0.w, w); fma4(acc1, a1.w, w); fma4(acc2, a2.w, w); fma4(acc3, a3.w, w);
    }

    float4 bv = *(const float4*)(bias + lane * 4);
    acc0.x += bv.x; acc0.y += bv.y; acc0.z += bv.z; acc0.w += bv.w;
    acc1.x += bv.x; acc1.y += bv.y; acc1.z += bv.z; acc1.w += bv.w;
    acc2.x += bv.x; acc2.y += bv.y; acc2.z += bv.z; acc2.w += bv.w;
    acc3.x += bv.x; acc3.y += bv.y; acc3.z += bv.z; acc3.w += bv.w;

    *(float4*)(C + (size_t)(row0 + 0) * DIM + lane * 4) = acc0;
    *(float4*)(C + (size_t)(row0 + 1) * DIM + lane * 4) = acc1;
    *(float4*)(C + (size_t)(row0 + 2) * DIM + lane * 4) = acc2;
    *(float4*)(C + (size_t)(row0 + 3) * DIM + lane * 4) = acc3;
}

// ---------------------------------------------------------------------------
// Layer start: xn = channel-normalize(x); s = per-lane group-of-4 sums of xn.
// ---------------------------------------------------------------------------
__global__ void norm_s_kernel(const float* __restrict__ in,
                              float* __restrict__ xn,
                              float* __restrict__ s_arr) {
    int gw   = (blockIdx.x * blockDim.x + threadIdx.x) >> 5;
    int lane = threadIdx.x & 31;
    if (gw >= N_NODES) return;

    size_t off = (size_t)gw * DIM + lane * 4;
    float4 v = *(const float4*)(in + off);
    float ss = v.x * v.x + v.y * v.y + v.z * v.z + v.w * v.w;
    ss += __shfl_xor_sync(0xffffffffu, ss, 1);
    ss += __shfl_xor_sync(0xffffffffu, ss, 2);
    ss += __shfl_xor_sync(0xffffffffu, ss, 4);   // channel = lane >> 3
    float inv = 1.0f / fmaxf(sqrtf(ss), 1e-12f);
    float4 o = {v.x * inv, v.y * inv, v.z * inv, v.w * inv};
    *(float4*)(xn + off) = o;
    s_arr[(size_t)gw * 32 + lane] = o.x + o.y + o.z + o.w;
}

// ---------------------------------------------------------------------------
// Routing pass, CSR form: one warp per TARGET node. No atomics.
//   sv        : this node's s slice (replicated x4 across 8-lane channel groups)
//   per edge  : gather z = xn[src], p = softmax_k(dot per channel), acc += p*z
//   end       : v = acc + xn[n];
//               write_full ? store v : store s_next = groupsum(normalize(v))
// ---------------------------------------------------------------------------
__global__ void route_csr_kernel(const int* __restrict__ scanned,
                                 const int* __restrict__ boff,
                                 const int* __restrict__ deg,
                                 const int* __restrict__ esrc,
                                 const float* __restrict__ xn,
                                 float* __restrict__ s_arr,
                                 float* __restrict__ out_v,
                                 int write_full) {
    int n    = (blockIdx.x * blockDim.x + threadIdx.x) >> 5;
    int lane = threadIdx.x & 31;
    if (n >= N_NODES) return;

    float4 sv = *(const float4*)(s_arr + (size_t)n * 32 + (lane & 7) * 4);
    float4 acc = {0.f, 0.f, 0.f, 0.f};

    int start = scanned[n] + boff[n >> 9];
    int d     = deg[n];

    for (int b = 0; b < d; b += 32) {
        int nb = min(32, d - b);
        int mysrc = (lane < nb) ? esrc[start + b + lane] : 0;
        for (int j = 0; j < nb; j++) {
            int src = __shfl_sync(0xffffffffu, mysrc, j);
            float4 zv = *(const float4*)(xn + (size_t)src * DIM + lane * 4);

            float part = zv.x * sv.x + zv.y * sv.y + zv.z * sv.z + zv.w * sv.w;
            part += __shfl_xor_sync(0xffffffffu, part, 1);
            part += __shfl_xor_sync(0xffffffffu, part, 2);
            part += __shfl_xor_sync(0xffffffffu, part, 4);   // channel dot

            float mx = fmaxf(part, __shfl_xor_sync(0xffffffffu, part, 8));
            mx = fmaxf(mx, __shfl_xor_sync(0xffffffffu, mx, 16));
            float e  = __expf(part - mx);
            float es = e;
            es += __shfl_xor_sync(0xffffffffu, es, 8);
            es += __shfl_xor_sync(0xffffffffu, es, 16);
            float pk = e / es;

            acc.x += pk * zv.x; acc.y += pk * zv.y;
            acc.z += pk * zv.z; acc.w += pk * zv.w;
        }
    }

    size_t off = (size_t)n * DIM + lane * 4;
    float4 xv = *(const float4*)(xn + off);
    float4 v  = {acc.x + xv.x, acc.y + xv.y, acc.z + xv.z, acc.w + xv.w};

    if (write_full) {
        *(float4*)(out_v + off) = v;
    } else {
        float ss = v.x * v.x + v.y * v.y + v.z * v.z + v.w * v.w;
        ss += __shfl_xor_sync(0xffffffffu, ss, 1);
        ss += __shfl_xor_sync(0xffffffffu, ss, 2);
        ss += __shfl_xor_sync(0xffffffffu, ss, 4);
        float inv = 1.0f / fmaxf(sqrtf(ss), 1e-12f);
        s_arr[(size_t)n * 32 + lane] = (v.x + v.y + v.z + v.w) * inv;
    }
}

// ---------------------------------------------------------------------------
extern "C" void kernel_launch(void* const* d_in, const int* in_sizes, int n_in,
                              void* d_out, int out_size) {
    const float* feat  = (const float*)d_in[0];
    const int*   eidx  = (const int*)  d_in[1];
    const float* lin_w = (const float*)d_in[2];
    const float* lin_b = (const float*)d_in[3];
    const float* mlp_w = (const float*)d_in[4];
    const float* mlp_b = (const float*)d_in[5];
    float*       out   = (float*)d_out;

    float *x0, *xn, *sarr;
    int *deg, *cnt, *scn, *bsum, *boff, *esrc;
    cudaGetSymbolAddress((void**)&x0,  g_x0);
    cudaGetSymbolAddress((void**)&xn,  g_xn);
    cudaGetSymbolAddress((void**)&sarr, g_s);
    cudaGetSymbolAddress((void**)&deg,  g_deg);
    cudaGetSymbolAddress((void**)&cnt,  g_cnt);
    cudaGetSymbolAddress((void**)&scn,  g_scan);
    cudaGetSymbolAddress((void**)&bsum, g_bsum);
    cudaGetSymbolAddress((void**)&boff, g_boff);
    cudaGetSymbolAddress((void**)&esrc, g_esrc);

    detect_dtype_kernel<<<1, 32>>>((const unsigned int*)d_in[1]);

    // ---- CSR build (graph fixed across all 6 edge passes) ----
    cudaMemsetAsync(deg, 0, N_NODES * sizeof(int), 0);
    cudaMemsetAsync(cnt, 0, N_NODES * sizeof(int), 0);
    const int eblk = (M_EDGES + 255) / 256;
    hist_kernel<<<eblk, 256>>>(eidx, deg);
    scan_phase1<<<NCHUNKS, CHUNK>>>(deg, scn, bsum);
    scan_phase2<<<1, 128>>>(bsum, boff);
    scatter_kernel<<<eblk, 256>>>(eidx, scn, boff, cnt, esrc);

    // ---- x0 = feat @ lin_w + lin_b ----
    const int gemm_blocks = ((N_NODES / 4) + 7) / 8;
    gemm_bias_kernel<<<gemm_blocks, 256>>>(feat, lin_w, lin_b, x0, N_NODES);

    const int node_blocks = (N_NODES + 7) / 8;   // 1 warp/node, 8 warps/block

    // ---- layer 0 ----
    norm_s_kernel<<<node_blocks, 256>>>(x0, xn, sarr);
    route_csr_kernel<<<node_blocks, 256>>>(scn, boff, deg, esrc, xn, sarr, x0, 0);
    route_csr_kernel<<<node_blocks, 256>>>(scn, boff, deg, esrc, xn, sarr, x0, 0);
    route_csr_kernel<<<node_blocks, 256>>>(scn, boff, deg, esrc, xn, sarr, x0, 1); // -> x0

    // ---- layer 1 ----
    float* out_tail = out + NF;
    norm_s_kernel<<<node_blocks, 256>>>(x0, xn, sarr);
    route_csr_kernel<<<node_blocks, 256>>>(scn, boff, deg, esrc, xn, sarr, out_tail, 0);
    route_csr_kernel<<<node_blocks, 256>>>(scn, boff, deg, esrc, xn, sarr, out_tail, 0);
    route_csr_kernel<<<node_blocks, 256>>>(scn, boff, deg, esrc, xn, sarr, out_tail, 1);

    // ---- out head = x_final @ mlp_w + mlp_b ----
    gemm_bias_kernel<<<gemm_blocks, 256>>>(out_tail, mlp_w, mlp_b, out, N_NODES);
}

// round 6
// speedup vs baseline: 2.0096x; 1.3115x over previous
#include <cuda_runtime.h>
#include <cstdint>

#define N_NODES 50000
#define DIM     128
#define M_EDGES 800000
#define NF      ((size_t)N_NODES * DIM)
#define CHUNK   512
#define NCHUNKS ((N_NODES + CHUNK - 1) / CHUNK)   // 98

// Route-kernel output modes
#define MODE_S_ONLY   0   // update s only (t<2)
#define MODE_FULL     1   // write unnormalized v (last layer end)
#define MODE_NORM     2   // write normalized v -> xn_next, s (layer transition)

// Scratch (__device__ globals; no allocations allowed).
__device__ __align__(256) float g_xnA[NF];                    // xn ping
__device__ __align__(256) float g_xnB[NF];                    // xn pong
__device__ __align__(256) float g_s  [(size_t)N_NODES * 32];  // per-node group sums
__device__ int g_deg [N_NODES];
__device__ int g_cnt [N_NODES];
__device__ int g_scan[N_NODES];
__device__ int g_bsum[NCHUNKS];
__device__ int g_boff[NCHUNKS];
__device__ int g_esrc[M_EDGES];
__device__ int g_is64;

// ---------------------------------------------------------------------------
__global__ void detect_dtype_kernel(const unsigned int* __restrict__ e) {
    if (threadIdx.x == 0) {
        int is64 = 1;
        for (int i = 0; i < 256; i++)
            if (e[2 * i + 1] != 0u) { is64 = 0; break; }
        g_is64 = is64;
    }
}

// ---------------------------------------------------------------------------
// CSR build: histogram -> 2-level exclusive scan -> scatter.
// ---------------------------------------------------------------------------
__global__ void hist_kernel(const int* __restrict__ eidx, int* __restrict__ deg) {
    int e = blockIdx.x * blockDim.x + threadIdx.x;
    if (e >= M_EDGES) return;
    int trg = g_is64 ? eidx[2 * ((size_t)M_EDGES + e)] : eidx[M_EDGES + e];
    atomicAdd(&deg[trg], 1);
}

__global__ void scan_phase1(const int* __restrict__ deg,
                            int* __restrict__ scanned, int* __restrict__ bsum) {
    __shared__ int sm[CHUNK];
    int i = blockIdx.x * CHUNK + threadIdx.x;
    int v = (i < N_NODES) ? deg[i] : 0;
    sm[threadIdx.x] = v;
    __syncthreads();
    for (int off = 1; off < CHUNK; off <<= 1) {
        int t = (threadIdx.x >= off) ? sm[threadIdx.x - off] : 0;
        __syncthreads();
        sm[threadIdx.x] += t;
        __syncthreads();
    }
    if (i < N_NODES) scanned[i] = sm[threadIdx.x] - v;
    if (threadIdx.x == CHUNK - 1) bsum[blockIdx.x] = sm[CHUNK - 1];
}

__global__ void scan_phase2(const int* __restrict__ bsum, int* __restrict__ boff) {
    __shared__ int sm[128];
    int t = threadIdx.x;
    int v = (t < NCHUNKS) ? bsum[t] : 0;
    sm[t] = v;
    __syncthreads();
    for (int off = 1; off < 128; off <<= 1) {
        int u = (t >= off) ? sm[t - off] : 0;
        __syncthreads();
        sm[t] += u;
        __syncthreads();
    }
    if (t < NCHUNKS) boff[t] = sm[t] - v;
}

__global__ void scatter_kernel(const int* __restrict__ eidx,
                               const int* __restrict__ scanned,
                               const int* __restrict__ boff,
                               int* __restrict__ cnt, int* __restrict__ esrc) {
    int e = blockIdx.x * blockDim.x + threadIdx.x;
    if (e >= M_EDGES) return;
    int src, trg;
    if (g_is64) {
        src = eidx[2 * (size_t)e];
        trg = eidx[2 * ((size_t)M_EDGES + e)];
    } else {
        src = eidx[e];
        trg = eidx[M_EDGES + e];
    }
    int pos = scanned[trg] + boff[trg >> 9] + atomicAdd(&cnt[trg], 1);
    esrc[pos] = src;
}

// ---------------------------------------------------------------------------
// GEMM helpers
// ---------------------------------------------------------------------------
__device__ __forceinline__ void fma4(float4& acc, float a, const float4& w) {
    acc.x += a * w.x; acc.y += a * w.y; acc.z += a * w.z; acc.w += a * w.w;
}

__device__ __forceinline__ void gemm_core(const float* __restrict__ a,
                                          const float* __restrict__ W,
                                          const float* __restrict__ bias,
                                          int lane,
                                          float4& acc0, float4& acc1,
                                          float4& acc2, float4& acc3) {
    acc0 = make_float4(0,0,0,0); acc1 = make_float4(0,0,0,0);
    acc2 = make_float4(0,0,0,0); acc3 = make_float4(0,0,0,0);
    #pragma unroll 2
    for (int k = 0; k < DIM; k += 4) {
        float4 a0 = *(const float4*)(a + 0 * DIM + k);
        float4 a1 = *(const float4*)(a + 1 * DIM + k);
        float4 a2 = *(const float4*)(a + 2 * DIM + k);
        float4 a3 = *(const float4*)(a + 3 * DIM + k);
        float4 w;
        w = *(const float4*)(W + (size_t)(k + 0) * DIM + lane * 4);
        fma4(acc0, a0.x, w); fma4(acc1, a1.x, w); fma4(acc2, a2.x, w); fma4(acc3, a3.x, w);
        w = *(const float4*)(W + (size_t)(k + 1) * DIM + lane * 4);
        fma4(acc0, a0.y, w); fma4(acc1, a1.y, w); fma4(acc2, a2.y, w); fma4(acc3, a3.y, w);
        w = *(const float4*)(W + (size_t)(k + 2) * DIM + lane * 4);
        fma4(acc0, a0.z, w); fma4(acc1, a1.z, w); fma4(acc2, a2.z, w); fma4(acc3, a3.z, w);
        w = *(const float4*)(W + (size_t)(k + 3) * DIM + lane * 4);
        fma4(acc0, a0.w, w); fma4(acc1, a1.w, w); fma4(acc2, a2.w, w); fma4(acc3, a3.w, w);
    }
    float4 bv = *(const float4*)(bias + lane * 4);
    acc0.x += bv.x; acc0.y += bv.y; acc0.z += bv.z; acc0.w += bv.w;
    acc1.x += bv.x; acc1.y += bv.y; acc1.z += bv.z; acc1.w += bv.w;
    acc2.x += bv.x; acc2.y += bv.y; acc2.z += bv.z; acc2.w += bv.w;
    acc3.x += bv.x; acc3.y += bv.y; acc3.z += bv.z; acc3.w += bv.w;
}

// Plain GEMM+bias (output head)
__global__ void gemm_bias_kernel(const float* __restrict__ A,
                                 const float* __restrict__ W,
                                 const float* __restrict__ bias,
                                 float* __restrict__ C, int nrows) {
    int gwarp = (blockIdx.x * blockDim.x + threadIdx.x) >> 5;
    int lane  = threadIdx.x & 31;
    int row0  = gwarp * 4;
    if (row0 >= nrows) return;
    float4 a0, a1, a2, a3;
    gemm_core(A + (size_t)row0 * DIM, W, bias, lane, a0, a1, a2, a3);
    *(float4*)(C + (size_t)(row0 + 0) * DIM + lane * 4) = a0;
    *(float4*)(C + (size_t)(row0 + 1) * DIM + lane * 4) = a1;
    *(float4*)(C + (size_t)(row0 + 2) * DIM + lane * 4) = a2;
    *(float4*)(C + (size_t)(row0 + 3) * DIM + lane * 4) = a3;
}

// GEMM+bias fused with channel-normalize + s computation (layer-0 entry).
// Writes xn and s directly; the unnormalized product is never materialized.
__device__ __forceinline__ void norm_row_store(float4 v, int row, int lane,
                                               float* __restrict__ xn,
                                               float* __restrict__ s_arr) {
    float ss = v.x * v.x + v.y * v.y + v.z * v.z + v.w * v.w;
    ss += __shfl_xor_sync(0xffffffffu, ss, 1);
    ss += __shfl_xor_sync(0xffffffffu, ss, 2);
    ss += __shfl_xor_sync(0xffffffffu, ss, 4);   // channel = lane >> 3
    float inv = 1.0f / fmaxf(sqrtf(ss), 1e-12f);
    float4 o = {v.x * inv, v.y * inv, v.z * inv, v.w * inv};
    *(float4*)(xn + (size_t)row * DIM + lane * 4) = o;
    s_arr[(size_t)row * 32 + lane] = o.x + o.y + o.z + o.w;
}

__global__ void gemm_norm_kernel(const float* __restrict__ A,
                                 const float* __restrict__ W,
                                 const float* __restrict__ bias,
                                 float* __restrict__ xn,
                                 float* __restrict__ s_arr, int nrows) {
    int gwarp = (blockIdx.x * blockDim.x + threadIdx.x) >> 5;
    int lane  = threadIdx.x & 31;
    int row0  = gwarp * 4;
    if (row0 >= nrows) return;
    float4 a0, a1, a2, a3;
    gemm_core(A + (size_t)row0 * DIM, W, bias, lane, a0, a1, a2, a3);
    norm_row_store(a0, row0 + 0, lane, xn, s_arr);
    norm_row_store(a1, row0 + 1, lane, xn, s_arr);
    norm_row_store(a2, row0 + 2, lane, xn, s_arr);
    norm_row_store(a3, row0 + 3, lane, xn, s_arr);
}

// ---------------------------------------------------------------------------
// Routing pass, CSR form: one warp per TARGET node, 4-edge ILP unroll.
// Softmax without max-subtraction (|dot| = |z_k . s| <= ||z_k||*||s|| <= 4).
// ---------------------------------------------------------------------------
__device__ __forceinline__ float edge_weight(const float4& zv, const float4& sv) {
    float p = zv.x * sv.x + zv.y * sv.y + zv.z * sv.z + zv.w * sv.w;
    p += __shfl_xor_sync(0xffffffffu, p, 1);
    p += __shfl_xor_sync(0xffffffffu, p, 2);
    p += __shfl_xor_sync(0xffffffffu, p, 4);      // per-channel dot
    float e  = __expf(p);
    float es = e;
    es += __shfl_xor_sync(0xffffffffu, es, 8);
    es += __shfl_xor_sync(0xffffffffu, es, 16);   // sum over 4 channels
    return __fdividef(e, es);
}

__global__ void route_csr_kernel(const int* __restrict__ scanned,
                                 const int* __restrict__ boff,
                                 const int* __restrict__ deg,
                                 const int* __restrict__ esrc,
                                 const float* __restrict__ xn,
                                 float* __restrict__ s_arr,
                                 float* __restrict__ out_v,
                                 float* __restrict__ s_out,
                                 int mode) {
    int n    = (blockIdx.x * blockDim.x + threadIdx.x) >> 5;
    int lane = threadIdx.x & 31;
    if (n >= N_NODES) return;

    const float4 sv = *(const float4*)(s_arr + (size_t)n * 32 + (lane & 7) * 4);
    float4 acc0 = {0,0,0,0}, acc1 = {0,0,0,0}, acc2 = {0,0,0,0}, acc3 = {0,0,0,0};

    int start = scanned[n] + boff[n >> 9];
    int d     = deg[n];

    for (int b = 0; b < d; b += 32) {
        int nb = min(32, d - b);
        int mysrc = (lane < nb) ? __ldg(&esrc[start + b + lane]) : 0;
        int j = 0;
        for (; j + 4 <= nb; j += 4) {
            int s0 = __shfl_sync(0xffffffffu, mysrc, j + 0);
            int s1 = __shfl_sync(0xffffffffu, mysrc, j + 1);
            int s2 = __shfl_sync(0xffffffffu, mysrc, j + 2);
            int s3 = __shfl_sync(0xffffffffu, mysrc, j + 3);
            float4 z0 = __ldg((const float4*)(xn + (size_t)s0 * DIM + lane * 4));
            float4 z1 = __ldg((const float4*)(xn + (size_t)s1 * DIM + lane * 4));
            float4 z2 = __ldg((const float4*)(xn + (size_t)s2 * DIM + lane * 4));
            float4 z3 = __ldg((const float4*)(xn + (size_t)s3 * DIM + lane * 4));
            float p0 = edge_weight(z0, sv);
            float p1 = edge_weight(z1, sv);
            float p2 = edge_weight(z2, sv);
            float p3 = edge_weight(z3, sv);
            acc0.x += p0 * z0.x; acc0.y += p0 * z0.y; acc0.z += p0 * z0.z; acc0.w += p0 * z0.w;
            acc1.x += p1 * z1.x; acc1.y += p1 * z1.y; acc1.z += p1 * z1.z; acc1.w += p1 * z1.w;
            acc2.x += p2 * z2.x; acc2.y += p2 * z2.y; acc2.z += p2 * z2.z; acc2.w += p2 * z2.w;
            acc3.x += p3 * z3.x; acc3.y += p3 * z3.y; acc3.z += p3 * z3.z; acc3.w += p3 * z3.w;
        }
        for (; j < nb; j++) {
            int s0 = __shfl_sync(0xffffffffu, mysrc, j);
            float4 z0 = __ldg((const float4*)(xn + (size_t)s0 * DIM + lane * 4));
            float p0 = edge_weight(z0, sv);
            acc0.x += p0 * z0.x; acc0.y += p0 * z0.y; acc0.z += p0 * z0.z; acc0.w += p0 * z0.w;
        }
    }

    size_t off = (size_t)n * DIM + lane * 4;
    float4 xv = *(const float4*)(xn + off);
    float4 v;
    v.x = acc0.x + acc1.x + acc2.x + acc3.x + xv.x;
    v.y = acc0.y + acc1.y + acc2.y + acc3.y + xv.y;
    v.z = acc0.z + acc1.z + acc2.z + acc3.z + xv.z;
    v.w = acc0.w + acc1.w + acc2.w + acc3.w + xv.w;

    if (mode == MODE_FULL) {
        *(float4*)(out_v + off) = v;
    } else {
        float ss = v.x * v.x + v.y * v.y + v.z * v.z + v.w * v.w;
        ss += __shfl_xor_sync(0xffffffffu, ss, 1);
        ss += __shfl_xor_sync(0xffffffffu, ss, 2);
        ss += __shfl_xor_sync(0xffffffffu, ss, 4);
        float inv = 1.0f / fmaxf(sqrtf(ss), 1e-12f);
        if (mode == MODE_S_ONLY) {
            s_arr[(size_t)n * 32 + lane] = (v.x + v.y + v.z + v.w) * inv;
        } else { // MODE_NORM: layer transition -> write normalized v + s
            float4 o = {v.x * inv, v.y * inv, v.z * inv, v.w * inv};
            *(float4*)(out_v + off) = o;
            s_out[(size_t)n * 32 + lane] = o.x + o.y + o.z + o.w;
        }
    }
}

// ---------------------------------------------------------------------------
extern "C" void kernel_launch(void* const* d_in, const int* in_sizes, int n_in,
                              void* d_out, int out_size) {
    const float* feat  = (const float*)d_in[0];
    const int*   eidx  = (const int*)  d_in[1];
    const float* lin_w = (const float*)d_in[2];
    const float* lin_b = (const float*)d_in[3];
    const float* mlp_w = (const float*)d_in[4];
    const float* mlp_b = (const float*)d_in[5];
    float*       out   = (float*)d_out;

    float *xnA, *xnB, *sarr;
    int *deg, *cnt, *scn, *bsum, *boff, *esrc;
    cudaGetSymbolAddress((void**)&xnA,  g_xnA);
    cudaGetSymbolAddress((void**)&xnB,  g_xnB);
    cudaGetSymbolAddress((void**)&sarr, g_s);
    cudaGetSymbolAddress((void**)&deg,  g_deg);
    cudaGetSymbolAddress((void**)&cnt,  g_cnt);
    cudaGetSymbolAddress((void**)&scn,  g_scan);
    cudaGetSymbolAddress((void**)&bsum, g_bsum);
    cudaGetSymbolAddress((void**)&boff, g_boff);
    cudaGetSymbolAddress((void**)&esrc, g_esrc);

    detect_dtype_kernel<<<1, 32>>>((const unsigned int*)d_in[1]);

    // ---- CSR build ----
    cudaMemsetAsync(deg, 0, N_NODES * sizeof(int), 0);
    cudaMemsetAsync(cnt, 0, N_NODES * sizeof(int), 0);
    const int eblk = (M_EDGES + 255) / 256;
    hist_kernel<<<eblk, 256>>>(eidx, deg);
    scan_phase1<<<NCHUNKS, CHUNK>>>(deg, scn, bsum);
    scan_phase2<<<1, 128>>>(bsum, boff);
    scatter_kernel<<<eblk, 256>>>(eidx, scn, boff, cnt, esrc);

    const int gemm_blocks = ((N_NODES / 4) + 7) / 8;
    const int node_blocks = (N_NODES + 7) / 8;

    // ---- layer 0 entry: fused GEMM + normalize + s ----
    gemm_norm_kernel<<<gemm_blocks, 256>>>(feat, lin_w, lin_b, xnA, sarr, N_NODES);

    // ---- layer 0 routing (t=2 writes normalized next-layer xn into xnB) ----
    route_csr_kernel<<<node_blocks, 256>>>(scn, boff, deg, esrc, xnA, sarr, nullptr, nullptr, MODE_S_ONLY);
    route_csr_kernel<<<node_blocks, 256>>>(scn, boff, deg, esrc, xnA, sarr, nullptr, nullptr, MODE_S_ONLY);
    route_csr_kernel<<<node_blocks, 256>>>(scn, boff, deg, esrc, xnA, sarr, xnB, sarr, MODE_NORM);

    // ---- layer 1 routing (t=2 writes unnormalized v straight to output tail) ----
    float* out_tail = out + NF;
    route_csr_kernel<<<node_blocks, 256>>>(scn, boff, deg, esrc, xnB, sarr, nullptr, nullptr, MODE_S_ONLY);
    route_csr_kernel<<<node_blocks, 256>>>(scn, boff, deg, esrc, xnB, sarr, nullptr, nullptr, MODE_S_ONLY);
    route_csr_kernel<<<node_blocks, 256>>>(scn, boff, deg, esrc, xnB, sarr, out_tail, nullptr, MODE_FULL);

    // ---- output head ----
    gemm_bias_kernel<<<gemm_blocks, 256>>>(out_tail, mlp_w, mlp_b, out, N_NODES);
}